// round 1
// baseline (speedup 1.0000x reference)
#include <cuda_runtime.h>

// Complex-valued attention, B=4 H=8 S=2048 D=64.
// out[2, B,H,S,D] = cv_softmax((Q/8) K^T) @ V   (complex, softmax on |z|, phase kept)
//
// Flash-style: 1 CTA = one (head, 64-row query tile). 256 threads (16x16),
// each thread owns 4x4 micro-tiles. fp32 throughout; inner products use
// sm_103a fma.rn.f32x2 packed over the reduction dimension (free pairs from
// LDS.128 fragments, even/odd partial sums folded at the end).

#define SLEN 2048
#define DH   64
#define BM   64
#define BN   64
#define NTILE (SLEN / BN)
#define PLANE (4 * 8 * 2048 * 64)
#define TEMP_INV 0.125f
#define SGN2 0x8000000080000000ULL

static __device__ __forceinline__ unsigned long long ffma2(unsigned long long a,
                                                           unsigned long long b,
                                                           unsigned long long c) {
    unsigned long long d;
    asm("fma.rn.f32x2 %0, %1, %2, %3;" : "=l"(d) : "l"(a), "l"(b), "l"(c));
    return d;
}
static __device__ __forceinline__ unsigned long long fmul2(unsigned long long a,
                                                           unsigned long long b) {
    unsigned long long d;
    asm("mul.rn.f32x2 %0, %1, %2;" : "=l"(d) : "l"(a), "l"(b));
    return d;
}
static __device__ __forceinline__ float2 up2(unsigned long long v) {
    float2 f;
    asm("mov.b64 {%0, %1}, %2;" : "=f"(f.x), "=f"(f.y) : "l"(v));
    return f;
}
static __device__ __forceinline__ unsigned long long pk2(float a, float b) {
    unsigned long long v;
    asm("mov.b64 %0, {%1, %2};" : "=l"(v) : "f"(a), "f"(b));
    return v;
}

__global__ __launch_bounds__(256, 1)
void cvattn_kernel(const float* __restrict__ qr, const float* __restrict__ qi,
                   const float* __restrict__ kr, const float* __restrict__ ki,
                   const float* __restrict__ vr, const float* __restrict__ vi,
                   float* __restrict__ out)
{
    extern __shared__ float sm[];
    // each tile: 64 rows x 64 floats, XOR-swizzled in 16B chunks
    float* sQr = sm;            // [m][d]
    float* sQi = sm + 4096;
    float* sKr = sm + 8192;     // [n][d]
    float* sKi = sm + 12288;
    float* sVr = sm + 16384;    // transposed: [d][n]
    float* sVi = sm + 20480;
    float* sPr = sm + 24576;    // [m][n]
    float* sPi = sm + 28672;

    const int tid = threadIdx.x;
    const int tx  = tid & 15;          // col group (keys / head-dim)
    const int ty  = tid >> 4;          // row group (queries)
    const int bh  = blockIdx.y;
    const int m0  = blockIdx.x << 6;

    const size_t hoff = (size_t)bh * (SLEN * DH);
    const float4* Q4r = (const float4*)(qr + hoff);
    const float4* Q4i = (const float4*)(qi + hoff);
    const float4* K4r = (const float4*)(kr + hoff);
    const float4* K4i = (const float4*)(ki + hoff);
    const float4* V4r = (const float4*)(vr + hoff);
    const float4* V4i = (const float4*)(vi + hoff);

    // ---- load Q tile once (scaled by 1/TEMPERATURE), swizzled [m][d] ----
#pragma unroll
    for (int i = 0; i < 4; ++i) {
        int f4 = tid + (i << 8);
        int m = f4 >> 4, dc = f4 & 15;
        int gi = ((m0 + m) << 4) + dc;
        float4 a = Q4r[gi];
        float4 b = Q4i[gi];
        a.x *= TEMP_INV; a.y *= TEMP_INV; a.z *= TEMP_INV; a.w *= TEMP_INV;
        b.x *= TEMP_INV; b.y *= TEMP_INV; b.z *= TEMP_INV; b.w *= TEMP_INV;
        int sa = (m << 6) + (((dc ^ (m >> 2)) & 15) << 2);
        *(float4*)(sQr + sa) = a;
        *(float4*)(sQi + sa) = b;
    }

    // O accumulators: packed over n-parity (fold lo+hi at the end)
    unsigned long long ore[4][4], oim[4][4];
#pragma unroll
    for (int r = 0; r < 4; ++r)
#pragma unroll
        for (int c = 0; c < 4; ++c) { ore[r][c] = 0ull; oim[r][c] = 0ull; }

    float mrun[4] = {-INFINITY, -INFINITY, -INFINITY, -INFINITY};
    float lrun[4] = {0.f, 0.f, 0.f, 0.f};

    for (int t = 0; t < NTILE; ++t) {
        __syncthreads();
        // ---- load K tile (swizzled [n][d]) and V tile (transposed [d][n]) ----
#pragma unroll
        for (int i = 0; i < 4; ++i) {
            int f4 = tid + (i << 8);
            int n = f4 >> 4, dc = f4 & 15;
            int gi = (((t << 6) + n) << 4) + dc;
            float4 a = K4r[gi];
            float4 b = K4i[gi];
            int sa = (n << 6) + (((dc ^ (n >> 2)) & 15) << 2);
            *(float4*)(sKr + sa) = a;
            *(float4*)(sKi + sa) = b;
            float4 c4 = V4r[gi];
            float4 d4 = V4i[gi];
            int d0 = dc << 2;
#pragma unroll
            for (int j = 0; j < 4; ++j) {
                int dd = d0 + j;
                int va = (dd << 6) + ((((n >> 2) ^ (dd >> 2)) & 15) << 2) + (n & 3);
                sVr[va] = (&c4.x)[j];
                sVi[va] = (&d4.x)[j];
            }
        }
        __syncthreads();

        // ---- S = (Q/T) K^T   (complex, NOT conjugated) ----
        // S_re = sum qr*kr - qi*ki ;  S_im = sum qr*ki + qi*kr
        unsigned long long sre[4][4], sim[4][4];
#pragma unroll
        for (int r = 0; r < 4; ++r)
#pragma unroll
            for (int c = 0; c < 4; ++c) { sre[r][c] = 0ull; sim[r][c] = 0ull; }

#pragma unroll 4
        for (int kc = 0; kc < 16; ++kc) {
            ulonglong2 aR[4], aI[4];
            int qoff = ((kc ^ ty) & 15) << 2;
#pragma unroll
            for (int r = 0; r < 4; ++r) {
                int row = (ty << 2) + r;
                aR[r] = *(const ulonglong2*)(sQr + (row << 6) + qoff);
                aI[r] = *(const ulonglong2*)(sQi + (row << 6) + qoff);
            }
            int koff = ((kc ^ tx) & 15) << 2;
#pragma unroll
            for (int c = 0; c < 4; ++c) {
                int col = (tx << 2) + c;
                const float* kp = sKr + (col << 6) + koff;
                ulonglong2 bR = *(const ulonglong2*)kp;
                ulonglong2 bI = *(const ulonglong2*)(kp + 4096);
                unsigned long long nbx = bI.x ^ SGN2;
                unsigned long long nby = bI.y ^ SGN2;
#pragma unroll
                for (int r = 0; r < 4; ++r) {
                    sre[r][c] = ffma2(aR[r].x, bR.x, sre[r][c]);
                    sre[r][c] = ffma2(aR[r].y, bR.y, sre[r][c]);
                    sre[r][c] = ffma2(aI[r].x, nbx, sre[r][c]);
                    sre[r][c] = ffma2(aI[r].y, nby, sre[r][c]);
                    sim[r][c] = ffma2(aR[r].x, bI.x, sim[r][c]);
                    sim[r][c] = ffma2(aR[r].y, bI.y, sim[r][c]);
                    sim[r][c] = ffma2(aI[r].x, bR.x, sim[r][c]);
                    sim[r][c] = ffma2(aI[r].y, bR.y, sim[r][c]);
                }
            }
        }

        // ---- online magnitude-softmax; build P = exp(mag-m)*z/max(mag,eps) ----
#pragma unroll
        for (int r = 0; r < 4; ++r) {
            float re[4], im[4], mg[4];
            float rowmax = -INFINITY;
#pragma unroll
            for (int c = 0; c < 4; ++c) {
                float2 e = up2(sre[r][c]);
                float2 f = up2(sim[r][c]);
                re[c] = e.x + e.y;
                im[c] = f.x + f.y;
                mg[c] = sqrtf(re[c] * re[c] + im[c] * im[c]);
                rowmax = fmaxf(rowmax, mg[c]);
            }
#pragma unroll
            for (int o = 8; o >= 1; o >>= 1)
                rowmax = fmaxf(rowmax, __shfl_xor_sync(0xffffffffu, rowmax, o, 16));
            float mn = fmaxf(mrun[r], rowmax);
            float sc = __expf(mrun[r] - mn);   // first tile: exp(-inf)=0
            float4 pr4, pi4;
            float ps = 0.f;
#pragma unroll
            for (int c = 0; c < 4; ++c) {
                float p = __expf(mg[c] - mn);
                ps += p;
                float inv = __fdividef(p, fmaxf(mg[c], 1e-12f));
                (&pr4.x)[c] = re[c] * inv;
                (&pi4.x)[c] = im[c] * inv;
            }
#pragma unroll
            for (int o = 8; o >= 1; o >>= 1)
                ps += __shfl_xor_sync(0xffffffffu, ps, o, 16);
            lrun[r] = lrun[r] * sc + ps;
            mrun[r] = mn;
            int row = (ty << 2) + r;
            int sa = (row << 6) + (((tx ^ ty) & 15) << 2);
            *(float4*)(sPr + sa) = pr4;
            *(float4*)(sPi + sa) = pi4;
            unsigned long long scp = pk2(sc, sc);
#pragma unroll
            for (int c = 0; c < 4; ++c) {
                ore[r][c] = fmul2(ore[r][c], scp);
                oim[r][c] = fmul2(oim[r][c], scp);
            }
        }
        __syncthreads();

        // ---- O += P V   (complex):  O_re += pr*vr - pi*vi ; O_im += pr*vi + pi*vr
#pragma unroll 4
        for (int nc = 0; nc < 16; ++nc) {
            ulonglong2 pR[4], pI[4];
            int poff = ((nc ^ ty) & 15) << 2;
#pragma unroll
            for (int r = 0; r < 4; ++r) {
                int row = (ty << 2) + r;
                pR[r] = *(const ulonglong2*)(sPr + (row << 6) + poff);
                pI[r] = *(const ulonglong2*)(sPi + (row << 6) + poff);
            }
            int voff = ((nc ^ tx) & 15) << 2;
#pragma unroll
            for (int c = 0; c < 4; ++c) {
                int col = (tx << 2) + c;                    // col = head-dim index
                const float* vp = sVr + (col << 6) + voff;
                ulonglong2 vR = *(const ulonglong2*)vp;
                ulonglong2 vI = *(const ulonglong2*)(vp + 4096);
                unsigned long long nvx = vI.x ^ SGN2;
                unsigned long long nvy = vI.y ^ SGN2;
#pragma unroll
                for (int r = 0; r < 4; ++r) {
                    ore[r][c] = ffma2(pR[r].x, vR.x, ore[r][c]);
                    ore[r][c] = ffma2(pR[r].y, vR.y, ore[r][c]);
                    ore[r][c] = ffma2(pI[r].x, nvx, ore[r][c]);
                    ore[r][c] = ffma2(pI[r].y, nvy, ore[r][c]);
                    oim[r][c] = ffma2(pR[r].x, vI.x, oim[r][c]);
                    oim[r][c] = ffma2(pR[r].y, vI.y, oim[r][c]);
                    oim[r][c] = ffma2(pI[r].x, vR.x, oim[r][c]);
                    oim[r][c] = ffma2(pI[r].y, vR.y, oim[r][c]);
                }
            }
        }
    }

    // ---- epilogue: fold packed pairs, divide by l, store both planes ----
    float4* OutR = (float4*)(out + hoff);
    float4* OutI = (float4*)(out + (size_t)PLANE + hoff);
#pragma unroll
    for (int r = 0; r < 4; ++r) {
        float invl = 1.0f / lrun[r];
        float4 o_r, o_i;
#pragma unroll
        for (int c = 0; c < 4; ++c) {
            float2 e = up2(ore[r][c]);
            float2 f = up2(oim[r][c]);
            (&o_r.x)[c] = (e.x + e.y) * invl;
            (&o_i.x)[c] = (f.x + f.y) * invl;
        }
        int gi = ((m0 + (ty << 2) + r) << 4) + tx;
        OutR[gi] = o_r;
        OutI[gi] = o_i;
    }
}

extern "C" void kernel_launch(void* const* d_in, const int* in_sizes, int n_in,
                              void* d_out, int out_size)
{
    (void)in_sizes; (void)n_in; (void)out_size;
    cudaFuncSetAttribute(cvattn_kernel,
                         cudaFuncAttributeMaxDynamicSharedMemorySize, 131072);
    dim3 grid(SLEN / BM, 32);   // 32 query tiles x (B*H = 32)
    cvattn_kernel<<<grid, 256, 131072>>>(
        (const float*)d_in[0], (const float*)d_in[1],
        (const float*)d_in[2], (const float*)d_in[3],
        (const float*)d_in[4], (const float*)d_in[5],
        (float*)d_out);
}

// round 2
// speedup vs baseline: 1.2047x; 1.2047x over previous
#include <cuda_runtime.h>

// Complex-valued attention, B=4 H=8 S=2048 D=64.
// out[2,B,H,S,D] = cv_softmax((Q/8) K^T) @ V  (softmax on |z|, phase kept)
//
// Flash-style, 1 CTA = (head, 64-query tile), 256 threads (16x16), 4x4
// micro-tiles, fp32 via sm_103a fma.rn.f32x2. Round 2: cp.async
// double-buffered K/V, 2 barriers/tile, row-packed PV (P staged transposed,
// V natural layout), rsqrt-fused softmax.

#define SLEN 2048
#define DH   64
#define NTILE 32
#define PLANE (4 * 8 * 2048 * 64)
#define TEMP_INV 0.125f
#define SGN2 0x8000000080000000ULL

static __device__ __forceinline__ unsigned long long ffma2(unsigned long long a,
                                                           unsigned long long b,
                                                           unsigned long long c) {
    unsigned long long d;
    asm("fma.rn.f32x2 %0, %1, %2, %3;" : "=l"(d) : "l"(a), "l"(b), "l"(c));
    return d;
}
static __device__ __forceinline__ unsigned long long fmul2(unsigned long long a,
                                                           unsigned long long b) {
    unsigned long long d;
    asm("mul.rn.f32x2 %0, %1, %2;" : "=l"(d) : "l"(a), "l"(b));
    return d;
}
static __device__ __forceinline__ float2 up2(unsigned long long v) {
    float2 f;
    asm("mov.b64 {%0, %1}, %2;" : "=f"(f.x), "=f"(f.y) : "l"(v));
    return f;
}
static __device__ __forceinline__ unsigned long long pk2(float a, float b) {
    unsigned long long v;
    asm("mov.b64 %0, {%1, %2};" : "=l"(v) : "f"(a), "f"(b));
    return v;
}
static __device__ __forceinline__ void cp16(float* dst, const float4* src) {
    unsigned a = (unsigned)__cvta_generic_to_shared(dst);
    asm volatile("cp.async.cg.shared.global [%0], [%1], 16;" :: "r"(a), "l"(src));
}

__global__ __launch_bounds__(256, 1)
void cvattn_kernel(const float* __restrict__ qr, const float* __restrict__ qi,
                   const float* __restrict__ kr, const float* __restrict__ ki,
                   const float* __restrict__ vr, const float* __restrict__ vi,
                   float* __restrict__ out)
{
    extern __shared__ float sm[];
    float* sQr   = sm;                 // [m][d] swizzled, 4096
    float* sQi   = sm + 4096;
    float* sKb   = sm + 8192;          // [buf][re/im][64x64], 2x8192
    float* sVb   = sm + 24576;         // [buf][re/im][64x64], 2x8192
    float* sPtr_ = sm + 40960;         // P^T [n][m], 4096
    float* sPti_ = sm + 45056;

    const int tid = threadIdx.x;
    const int tx  = tid & 15;
    const int ty  = tid >> 4;
    const int bh  = blockIdx.y;
    const int m0  = blockIdx.x << 6;

    const size_t hoff = (size_t)bh * (SLEN * DH);
    const float4* K4r = (const float4*)(kr + hoff);
    const float4* K4i = (const float4*)(ki + hoff);
    const float4* V4r = (const float4*)(vr + hoff);
    const float4* V4i = (const float4*)(vi + hoff);

    // ---- Q tile once (scaled), swizzled [m][d] ----
    {
        const float4* Q4r = (const float4*)(qr + hoff);
        const float4* Q4i = (const float4*)(qi + hoff);
#pragma unroll
        for (int i = 0; i < 4; ++i) {
            int f4 = tid + (i << 8);
            int m = f4 >> 4, dc = f4 & 15;
            int gi = ((m0 + m) << 4) + dc;
            float4 a = Q4r[gi];
            float4 b = Q4i[gi];
            a.x *= TEMP_INV; a.y *= TEMP_INV; a.z *= TEMP_INV; a.w *= TEMP_INV;
            b.x *= TEMP_INV; b.y *= TEMP_INV; b.z *= TEMP_INV; b.w *= TEMP_INV;
            int sa = (m << 6) + (((dc ^ (m >> 2)) & 15) << 2);
            *(float4*)(sQr + sa) = a;
            *(float4*)(sQi + sa) = b;
        }
    }

    // ---- prefetch K/V tile 0 into buffer 0 ----
#pragma unroll
    for (int i = 0; i < 4; ++i) {
        int f4 = tid + (i << 8);
        int n = f4 >> 4, dc = f4 & 15;
        int gi = (n << 4) + dc;
        int sa = (n << 6) + (((dc ^ (n >> 2)) & 15) << 2);
        cp16(sKb + sa,        K4r + gi);
        cp16(sKb + 4096 + sa, K4i + gi);
        cp16(sVb + sa,        V4r + gi);
        cp16(sVb + 4096 + sa, V4i + gi);
    }
    asm volatile("cp.async.commit_group;" ::: "memory");

    // O accumulators: row-pair packed (rows ty*4+{0,1} | {2,3}), 3 sets
    unsigned long long oA[2][4], oB[2][4], oI[2][4];
#pragma unroll
    for (int p = 0; p < 2; ++p)
#pragma unroll
        for (int c = 0; c < 4; ++c) { oA[p][c] = 0ull; oB[p][c] = 0ull; oI[p][c] = 0ull; }

    float mrun[4] = {-INFINITY, -INFINITY, -INFINITY, -INFINITY};
    float lrun[4] = {0.f, 0.f, 0.f, 0.f};

    asm volatile("cp.async.wait_group 0;" ::: "memory");
    __syncthreads();

    for (int t = 0; t < NTILE; ++t) {
        const int cur = t & 1;
        float* kb = sKb + (cur << 13);
        float* vb = sVb + (cur << 13);

        // ---- prefetch next tile into the other buffer ----
        if (t + 1 < NTILE) {
            float* kn = sKb + ((cur ^ 1) << 13);
            float* vn = sVb + ((cur ^ 1) << 13);
#pragma unroll
            for (int i = 0; i < 4; ++i) {
                int f4 = tid + (i << 8);
                int n = f4 >> 4, dc = f4 & 15;
                int gi = ((((t + 1) << 6) + n) << 4) + dc;
                int sa = (n << 6) + (((dc ^ (n >> 2)) & 15) << 2);
                cp16(kn + sa,        K4r + gi);
                cp16(kn + 4096 + sa, K4i + gi);
                cp16(vn + sa,        V4r + gi);
                cp16(vn + 4096 + sa, V4i + gi);
            }
        }
        asm volatile("cp.async.commit_group;" ::: "memory");

        // ---- S = (Q/T) K^T  (complex), reduction-packed over d ----
        unsigned long long sre[4][4], sim[4][4];
#pragma unroll
        for (int r = 0; r < 4; ++r)
#pragma unroll
            for (int c = 0; c < 4; ++c) { sre[r][c] = 0ull; sim[r][c] = 0ull; }

#pragma unroll 4
        for (int kc = 0; kc < 16; ++kc) {
            ulonglong2 aR[4], aI[4];
            int qoff = ((kc ^ ty) & 15) << 2;
#pragma unroll
            for (int r = 0; r < 4; ++r) {
                int row = (ty << 2) + r;
                aR[r] = *(const ulonglong2*)(sQr + (row << 6) + qoff);
                aI[r] = *(const ulonglong2*)(sQi + (row << 6) + qoff);
            }
            int koff = ((kc ^ tx) & 15) << 2;
#pragma unroll
            for (int c = 0; c < 4; ++c) {
                int col = (tx << 2) + c;
                const float* kp = kb + (col << 6) + koff;
                ulonglong2 bR = *(const ulonglong2*)kp;
                ulonglong2 bI = *(const ulonglong2*)(kp + 4096);
                unsigned long long nbx = bI.x ^ SGN2;
                unsigned long long nby = bI.y ^ SGN2;
#pragma unroll
                for (int r = 0; r < 4; ++r) {
                    sre[r][c] = ffma2(aR[r].x, bR.x, sre[r][c]);
                    sre[r][c] = ffma2(aR[r].y, bR.y, sre[r][c]);
                    sre[r][c] = ffma2(aI[r].x, nbx, sre[r][c]);
                    sre[r][c] = ffma2(aI[r].y, nby, sre[r][c]);
                    sim[r][c] = ffma2(aR[r].x, bI.x, sim[r][c]);
                    sim[r][c] = ffma2(aR[r].y, bI.y, sim[r][c]);
                    sim[r][c] = ffma2(aI[r].x, bR.x, sim[r][c]);
                    sim[r][c] = ffma2(aI[r].y, bR.y, sim[r][c]);
                }
            }
        }

        // ---- online magnitude-softmax ----
        float prv[4][4], piv[4][4], sc[4];
#pragma unroll
        for (int r = 0; r < 4; ++r) {
            float re[4], im[4], mg[4], ri[4];
            float rowmax = -INFINITY;
#pragma unroll
            for (int c = 0; c < 4; ++c) {
                float2 e = up2(sre[r][c]);
                float2 f = up2(sim[r][c]);
                re[c] = e.x + e.y;
                im[c] = f.x + f.y;
                float r2 = re[c] * re[c] + im[c] * im[c];
                ri[c] = rsqrtf(fmaxf(r2, 1e-24f));   // = 1/max(|z|,1e-12)
                mg[c] = r2 * ri[c];                  // = |z| (0 at z=0)
                rowmax = fmaxf(rowmax, mg[c]);
            }
#pragma unroll
            for (int o = 8; o >= 1; o >>= 1)
                rowmax = fmaxf(rowmax, __shfl_xor_sync(0xffffffffu, rowmax, o, 16));
            float mn = fmaxf(mrun[r], rowmax);
            sc[r] = __expf(mrun[r] - mn);
            float ps = 0.f;
#pragma unroll
            for (int c = 0; c < 4; ++c) {
                float p = __expf(mg[c] - mn);
                ps += p;
                float w = p * ri[c];
                prv[r][c] = re[c] * w;
                piv[r][c] = im[c] * w;
            }
#pragma unroll
            for (int o = 8; o >= 1; o >>= 1)
                ps += __shfl_xor_sync(0xffffffffu, ps, o, 16);
            lrun[r] = lrun[r] * sc[r] + ps;
            mrun[r] = mn;
        }
        // rescale O (row-pair packed)
        {
            unsigned long long s01 = pk2(sc[0], sc[1]);
            unsigned long long s23 = pk2(sc[2], sc[3]);
#pragma unroll
            for (int c = 0; c < 4; ++c) {
                oA[0][c] = fmul2(oA[0][c], s01); oA[1][c] = fmul2(oA[1][c], s23);
                oB[0][c] = fmul2(oB[0][c], s01); oB[1][c] = fmul2(oB[1][c], s23);
                oI[0][c] = fmul2(oI[0][c], s01); oI[1][c] = fmul2(oI[1][c], s23);
            }
        }
        // store P^T [n][m] (vectorized over the thread's 4 rows)
#pragma unroll
        for (int c = 0; c < 4; ++c) {
            int n = (tx << 2) + c;
            int sa = (n << 6) + (((ty ^ tx) & 15) << 2);
            *(float4*)(sPtr_ + sa) = make_float4(prv[0][c], prv[1][c], prv[2][c], prv[3][c]);
            *(float4*)(sPti_ + sa) = make_float4(piv[0][c], piv[1][c], piv[2][c], piv[3][c]);
        }
        __syncthreads();   // P^T visible to all

        // ---- O += P V  (row-pair packed; V natural [n][d]) ----
        //  oA += pr*vr ; oB += pi*vi ; oI += pr*vi + pi*vr ;  O_re = oA - oB
#pragma unroll 2
        for (int nc = 0; nc < 16; ++nc) {
            int poff = ((ty ^ nc) & 15) << 2;
            int voff = ((tx ^ nc) & 15) << 2;
#pragma unroll
            for (int j = 0; j < 4; ++j) {
                int n = (nc << 2) + j;
                const float* pp = sPtr_ + (n << 6) + poff;
                ulonglong2 pR = *(const ulonglong2*)pp;
                ulonglong2 pI = *(const ulonglong2*)(pp + 4096);
                const float* vp = vb + (n << 6) + voff;
                float4 v_r = *(const float4*)vp;
                float4 v_i = *(const float4*)(vp + 4096);
#pragma unroll
                for (int c = 0; c < 4; ++c) {
                    unsigned long long vrb = pk2((&v_r.x)[c], (&v_r.x)[c]);
                    unsigned long long vib = pk2((&v_i.x)[c], (&v_i.x)[c]);
                    oA[0][c] = ffma2(pR.x, vrb, oA[0][c]);
                    oA[1][c] = ffma2(pR.y, vrb, oA[1][c]);
                    oB[0][c] = ffma2(pI.x, vib, oB[0][c]);
                    oB[1][c] = ffma2(pI.y, vib, oB[1][c]);
                    oI[0][c] = ffma2(pR.x, vib, oI[0][c]);
                    oI[1][c] = ffma2(pR.y, vib, oI[1][c]);
                    oI[0][c] = ffma2(pI.x, vrb, oI[0][c]);
                    oI[1][c] = ffma2(pI.y, vrb, oI[1][c]);
                }
            }
        }

        asm volatile("cp.async.wait_group 0;" ::: "memory");
        __syncthreads();   // next K/V ready; P^T consumed
    }

    // ---- epilogue ----
    float4* OutR = (float4*)(out + hoff);
    float4* OutI = (float4*)(out + (size_t)PLANE + hoff);
    float invl[4];
#pragma unroll
    for (int r = 0; r < 4; ++r) invl[r] = 1.0f / lrun[r];
#pragma unroll
    for (int p = 0; p < 2; ++p) {
        float4 oR0, oI0, oR1, oI1;
        float i0 = invl[p * 2], i1 = invl[p * 2 + 1];
#pragma unroll
        for (int c = 0; c < 4; ++c) {
            float2 ea = up2(oA[p][c]);
            float2 eb = up2(oB[p][c]);
            float2 fi = up2(oI[p][c]);
            (&oR0.x)[c] = (ea.x - eb.x) * i0;
            (&oI0.x)[c] = fi.x * i0;
            (&oR1.x)[c] = (ea.y - eb.y) * i1;
            (&oI1.x)[c] = fi.y * i1;
        }
        int row0 = m0 + (ty << 2) + p * 2;
        int gi0 = (row0 << 4) + tx;
        int gi1 = ((row0 + 1) << 4) + tx;
        OutR[gi0] = oR0; OutI[gi0] = oI0;
        OutR[gi1] = oR1; OutI[gi1] = oI1;
    }
}

extern "C" void kernel_launch(void* const* d_in, const int* in_sizes, int n_in,
                              void* d_out, int out_size)
{
    (void)in_sizes; (void)n_in; (void)out_size;
    cudaFuncSetAttribute(cvattn_kernel,
                         cudaFuncAttributeMaxDynamicSharedMemorySize, 196608);
    dim3 grid(SLEN / 64, 32);
    cvattn_kernel<<<grid, 256, 196608>>>(
        (const float*)d_in[0], (const float*)d_in[1],
        (const float*)d_in[2], (const float*)d_in[3],
        (const float*)d_in[4], (const float*)d_in[5],
        (float*)d_out);
}